// round 17
// baseline (speedup 1.0000x reference)
#include <cuda_runtime.h>
#include <cstdint>
#include <cstddef>

#define T_STEPS 512
#define BATCH   64
#define EMBED   512
#define HIDDEN  1024
#define G4      4096           // 4*HIDDEN gate rows
#define NCLS    10
#define NCTA    128            // persistent grid (<=148 SMs, co-resident)
#define WSLD    68             // precompute W-tile smem pad
#define WROW    132            // row-major W tile row stride (128 + 4-float pad)
#define PSTR    36             // partial-tile row stride (mult of 4: float4-aligned)
#define TILE_F  4352           // floats per pair tile (17KB; holds 32*WROW=4224)
#define SMEM_BYTES (8 * TILE_F * 4)   // 136KB: 8 pair W-tiles / partials

// ---------------- device-global state (no allocations allowed) ----------------
__device__ float g_X0[(size_t)T_STEPS * G4 * BATCH];   // b0 + x-part of layer0 gates, [t][r][b]
__device__ float g_h0buf[2][HIDDEN * BATCH];           // ping-pong, [k][b]
__device__ float g_h1buf[2][HIDDEN * BATCH];
__device__ unsigned g_cA, g_cB;                        // monotonic barrier counters

// ---------------- packed fp32x2 FMA (bit-identical to 2x scalar FFMA) ----------------
__device__ __forceinline__ float2 ffma2(float2 a, float2 b, float2 c) {
    unsigned long long ua = *reinterpret_cast<unsigned long long*>(&a);
    unsigned long long ub = *reinterpret_cast<unsigned long long*>(&b);
    unsigned long long uc = *reinterpret_cast<unsigned long long*>(&c);
    asm("fma.rn.f32x2 %0, %1, %2, %0;" : "+l"(uc) : "l"(ua), "l"(ub));
    return *reinterpret_cast<float2*>(&uc);
}

// ---------------- fast gate nonlinearities (MUFU-based) ----------------
__device__ __forceinline__ float sigf(float v) {
    return __fdividef(1.0f, 1.0f + __expf(-v));
}
__device__ __forceinline__ float tanh_fast(float v) {
    float a = fabsf(v);
    float e = __expf(-2.0f * a);
    float t = __fdividef(1.0f - e, 1.0f + e);
    return copysignf(t, v);
}

// pair barrier: warps 2s, 2s+1 (64 threads), HW barrier id s+1
__device__ __forceinline__ void barp(int s) {
    asm volatile("bar.sync %0, 64;" :: "r"(s + 1) : "memory");
}

// Elected-lane spin on a monotonic counter + acquire fence, then pair barrier.
__device__ __forceinline__ void ctr_wait(unsigned* ctr, unsigned target, int s, int pt) {
    if (pt == 0) {
        while (*(volatile unsigned*)ctr < target) { __nanosleep(32); }
        __threadfence();                // acquire + CCTL.IVALL (SM-wide L1 inval)
    }
    barp(s);
}

// =====================================================================
// Precompute X0[t][r][b] = b0[r] + sum_e emb[x[b][t]][e] * W0[r][e]
// grid (T_STEPS, 64 row-tiles), 128 threads. t==0 blocks zero the state.
// =====================================================================
__global__ __launch_bounds__(128) void precompute_x0(
    const int* __restrict__ x, const float* __restrict__ emb,
    const float* __restrict__ W0, const float* __restrict__ b0)
{
    __shared__ float Hs[32 * 64];
    __shared__ float Ws[32 * WSLD];
    __shared__ int   sidx[64];

    const int tid   = threadIdx.x;
    const int t     = blockIdx.x;
    const int rbase = blockIdx.y * 64;

    if (t == 0) {
        int base = blockIdx.y * 1024 + tid * 8;
#pragma unroll
        for (int i2 = 0; i2 < 8; i2++) {
            g_h0buf[0][base + i2] = 0.f; g_h0buf[1][base + i2] = 0.f;
            g_h1buf[0][base + i2] = 0.f; g_h1buf[1][base + i2] = 0.f;
        }
        if (blockIdx.y == 0 && tid == 0) { g_cA = 0u; g_cB = 0u; }
    }

    if (tid < 64) sidx[tid] = x[tid * T_STEPS + t];
    __syncthreads();

    const int tb   = tid & 7;
    const int tr   = tid >> 3;
    const int ldrr = tid >> 1;
    const int ldk0 = (tid & 1) * 16;
    const int eb   = tid >> 1;
    const int ek0  = (tid & 1) * 16;

    float2 acc[4][4];
#pragma unroll
    for (int r = 0; r < 4; r++)
#pragma unroll
        for (int p = 0; p < 4; p++) acc[r][p] = make_float2(0.f, 0.f);

    const float* wbase = W0 + (size_t)(rbase + ldrr) * (EMBED + HIDDEN) + ldk0;
    const float* ebase = emb + (size_t)sidx[eb] * EMBED + ek0;

    for (int kt = 0; kt < EMBED; kt += 32) {
#pragma unroll
        for (int i = 0; i < 4; i++) {
            float4 v = *(const float4*)(ebase + kt + i * 4);
            Hs[(ek0 + i * 4 + 0) * 64 + eb] = v.x;
            Hs[(ek0 + i * 4 + 1) * 64 + eb] = v.y;
            Hs[(ek0 + i * 4 + 2) * 64 + eb] = v.z;
            Hs[(ek0 + i * 4 + 3) * 64 + eb] = v.w;
        }
#pragma unroll
        for (int i = 0; i < 4; i++) {
            float4 v = *(const float4*)(wbase + kt + i * 4);
            Ws[(ldk0 + i * 4 + 0) * WSLD + ldrr] = v.x;
            Ws[(ldk0 + i * 4 + 1) * WSLD + ldrr] = v.y;
            Ws[(ldk0 + i * 4 + 2) * WSLD + ldrr] = v.z;
            Ws[(ldk0 + i * 4 + 3) * WSLD + ldrr] = v.w;
        }
        __syncthreads();
#pragma unroll 8
        for (int kk = 0; kk < 32; kk++) {
            float4 wv = *(const float4*)&Ws[kk * WSLD + tr * 4];
            float4 ha = *(const float4*)&Hs[kk * 64 + tb * 8];
            float4 hb = *(const float4*)&Hs[kk * 64 + tb * 8 + 4];
            float2 h2[4] = { {ha.x, ha.y}, {ha.z, ha.w}, {hb.x, hb.y}, {hb.z, hb.w} };
            float  wr[4] = { wv.x, wv.y, wv.z, wv.w };
#pragma unroll
            for (int r = 0; r < 4; r++) {
                float2 w2 = make_float2(wr[r], wr[r]);
#pragma unroll
                for (int p = 0; p < 4; p++) acc[r][p] = ffma2(h2[p], w2, acc[r][p]);
            }
        }
        __syncthreads();
    }

#pragma unroll
    for (int r = 0; r < 4; r++) {
        int row = rbase + tr * 4 + r;
        float bb = b0[row];
        float* o = g_X0 + ((size_t)t * G4 + row) * BATCH + tb * 8;
        *(float4*)o       = make_float4(acc[r][0].x + bb, acc[r][0].y + bb,
                                        acc[r][1].x + bb, acc[r][1].y + bb);
        *(float4*)(o + 4) = make_float4(acc[r][2].x + bb, acc[r][2].y + bb,
                                        acc[r][3].x + bb, acc[r][3].y + bb);
    }
}

// =====================================================================
// Stage a 32-row x 128-k slice of W into smem, ROW-MAJOR [rr][WROW].
// Local row rr <-> global gate row (rr>>3)*HIDDEN + cbase + (rr&7).
// Pair-cooperative (64 threads): thread = (parity pt&1, kc = pt>>1).
// Per j: rows {2j, 2j+1}; each LDG.128's lanes cover 2 rows x 64 k
// = 8 gmem lines (vs 32 for the old transposed gather). STS.128 aligned.
// =====================================================================
__device__ __forceinline__ void stage_W(
    const float* __restrict__ W, int ldw, int col0, int cbase,
    float* Wt, int pt)
{
    const int par = pt & 1;
    const int kc  = pt >> 1;          // 0..31, covers k = kc*4..kc*4+3
#pragma unroll
    for (int j = 0; j < 16; j++) {
        const int rr = j * 2 + par;
        const int q = rr >> 3, i = rr & 7;
        float4 v = *(const float4*)(W + (size_t)(q * HIDDEN + cbase + i) * ldw
                                      + col0 + kc * 4);
        *(float4*)(Wt + rr * WROW + kc * 4) = v;
    }
}

// 16 FFMA2 for one k: H float4 (4 batch) x 8 row-weights (component C of wv[]).
#define KSTEP(H, C) do {                                                        \
    float2 hA = make_float2((H).x, (H).y);                                      \
    float2 hB = make_float2((H).z, (H).w);                                      \
    float2 w2;                                                                  \
    w2 = make_float2(wv[0].C, wv[0].C); acc[0][0] = ffma2(hA, w2, acc[0][0]); acc[0][1] = ffma2(hB, w2, acc[0][1]); \
    w2 = make_float2(wv[1].C, wv[1].C); acc[1][0] = ffma2(hA, w2, acc[1][0]); acc[1][1] = ffma2(hB, w2, acc[1][1]); \
    w2 = make_float2(wv[2].C, wv[2].C); acc[2][0] = ffma2(hA, w2, acc[2][0]); acc[2][1] = ffma2(hB, w2, acc[2][1]); \
    w2 = make_float2(wv[3].C, wv[3].C); acc[3][0] = ffma2(hA, w2, acc[3][0]); acc[3][1] = ffma2(hB, w2, acc[3][1]); \
    w2 = make_float2(wv[4].C, wv[4].C); acc[4][0] = ffma2(hA, w2, acc[4][0]); acc[4][1] = ffma2(hB, w2, acc[4][1]); \
    w2 = make_float2(wv[5].C, wv[5].C); acc[5][0] = ffma2(hA, w2, acc[5][0]); acc[5][1] = ffma2(hB, w2, acc[5][1]); \
    w2 = make_float2(wv[6].C, wv[6].C); acc[6][0] = ffma2(hA, w2, acc[6][0]); acc[6][1] = ffma2(hB, w2, acc[6][1]); \
    w2 = make_float2(wv[7].C, wv[7].C); acc[7][0] = ffma2(hA, w2, acc[7][0]); acc[7][1] = ffma2(hB, w2, acc[7][1]); \
} while (0)

// =====================================================================
// 128-k GEMM chunk: warp tile 32 rows x 32 batch, thread 8r x 4b.
// Lane rows = rg + 4*i (stride-4: with WROW=132 pad the 4 rg-groups land
// on distinct 16B bank offsets -> conflict-free LDS.128).
// Per k per warp: 2 LDS.128 (W) + 1 LDG.128 (H). H double-buffered in
// 4-k blocks (lead = 4k > L2 latency under 4-warp interleave).
// =====================================================================
__device__ __forceinline__ void gemm128(
    const float* __restrict__ hp,     // hsrc + koff*64 + hf*32 + bg*4
    const float* __restrict__ wt,     // pair tile base (row-major)
    int rg, float2 (&acc)[8][2])
{
    const float* wr0 = wt + rg * WROW;     // rows rg + 4*i at stride 4*WROW
    float4 h0[4], h1[4];
#pragma unroll
    for (int u = 0; u < 4; u++) h0[u] = *(const float4*)(hp + u * 64);

#pragma unroll 1
    for (int kb = 0; kb < 128; kb += 8) {
        // ---- sub-block A: k = kb..kb+3 (H in h0; prefetch h1 = kb+4..kb+7) ----
        {
            float4 wv[8];
#pragma unroll
            for (int i = 0; i < 8; i++)
                wv[i] = *(const float4*)(wr0 + (4 * i) * WROW + kb);
#pragma unroll
            for (int u = 0; u < 4; u++)
                h1[u] = *(const float4*)(hp + (kb + 4 + u) * 64);
            KSTEP(h0[0], x);
            KSTEP(h0[1], y);
            KSTEP(h0[2], z);
            KSTEP(h0[3], w);
        }
        // ---- sub-block B: k = kb+4..kb+7 (H in h1; prefetch h0 = kb+8..kb+11) ----
        {
            float4 wv[8];
#pragma unroll
            for (int i = 0; i < 8; i++)
                wv[i] = *(const float4*)(wr0 + (4 * i) * WROW + kb + 4);
#pragma unroll
            for (int u = 0; u < 4; u++) {
                int kn = kb + 8 + u; if (kn > 127) kn = 127;   // clamped tail
                h0[u] = *(const float4*)(hp + kn * 64);
            }
            KSTEP(h1[0], x);
            KSTEP(h1[1], y);
            KSTEP(h1[2], z);
            KSTEP(h1[3], w);
        }
    }
}

// Write the warp's 32x32 partial into its pair-half slice: 8 aligned STS.128.
// acc[i] holds local row rg+4*i, batch cols bg*4..bg*4+3.
__device__ __forceinline__ void write_partial(float2 (&acc)[8][2], float* part,
                                              int rg, int bg)
{
#pragma unroll
    for (int i = 0; i < 8; i++) {
        float4 v = make_float4(acc[i][0].x, acc[i][0].y, acc[i][1].x, acc[i][1].y);
        *(float4*)(part + (rg + 4 * i) * PSTR + bg * 4) = v;
    }
}

// =====================================================================
// Persistent kernel: CTA owns 8 hidden units (32 gate rows) for BOTH layers.
// 512 threads = 16 warps = 8 K-splits x 2 batch-halves.
// Release = grid_group::sync pattern (CTA barrier + tid0 cumulative fence).
// After the loop, CTA 0 computes the classifier.
// =====================================================================
__global__ __launch_bounds__(512, 1) void lstm_persistent(
    const float* __restrict__ W0, const float* __restrict__ W1,
    const float* __restrict__ b1,
    const float* __restrict__ V, const float* __restrict__ bV,
    float* __restrict__ out)
{
    extern __shared__ float dsm[];    // 8 pair tiles of TILE_F floats

    const int tid   = threadIdx.x;
    const int w     = tid >> 5;
    const int lane  = tid & 31;
    const int s     = w >> 1;         // K-split 0..7
    const int hf    = w & 1;          // batch half
    const int pt    = tid & 63;       // pair-local thread
    const int rg    = lane & 3;       // row group: rows rg+4i (8 rows)
    const int bg    = lane >> 2;      // batch group (4 batch)
    const int cbase = blockIdx.x * 8;
    const int jl    = tid >> 6;       // cell phase: local hidden unit 0..7
    const int b     = tid & 63;       // cell phase: batch lane

    float* Wt   = dsm + s * TILE_F;
    float* part = Wt + hf * (32 * PSTR);
    const int hoff = hf * 32 + bg * 4;

    float c0 = 0.f, c1 = 0.f;         // register-resident cell state
    float b1r[4];
#pragma unroll
    for (int q = 0; q < 4; q++) b1r[q] = b1[q * HIDDEN + cbase + jl];

    for (int t = 0; t < T_STEPS; t++) {
        const int p = t & 1;
        const float* h0_old = g_h0buf[p];
        float*       h0_new = g_h0buf[p ^ 1];
        const float* h1_old = g_h1buf[p];
        float*       h1_new = g_h1buf[p ^ 1];

        // prefetch this thread's X0 gate values (DRAM latency hides under GEMM)
        const float* X0t = g_X0 + (size_t)t * G4 * BATCH;
        float x0r[4];
#pragma unroll
        for (int q = 0; q < 4; q++)
            x0r[q] = X0t[(size_t)(q * HIDDEN + cbase + jl) * BATCH + b];

        // ---- layer 0: gates = X0[t] + W0[:, E:E+H] @ h0_old ----
        float2 acc[8][2];
#pragma unroll
        for (int i = 0; i < 8; i++) { acc[i][0] = make_float2(0.f, 0.f);
                                      acc[i][1] = make_float2(0.f, 0.f); }

        stage_W(W0, EMBED + HIDDEN, EMBED + s * 128, cbase, Wt, pt);
        barp(s);
        gemm128(h0_old + (size_t)(s * 128) * 64 + hoff, Wt, rg, acc);
        barp(s);                      // pair done reading Wt -> alias as partials
        write_partial(acc, part, rg, bg);
        __syncthreads();
        {
            const float* pb = dsm + (b >> 5) * (32 * PSTR) + (b & 31);
            float gs[4];
#pragma unroll
            for (int q = 0; q < 4; q++) {
                float v = x0r[q];
#pragma unroll
                for (int ss = 0; ss < 8; ss++)
                    v += pb[ss * TILE_F + (q * 8 + jl) * PSTR];
                gs[q] = v;
            }
            float cn = sigf(gs[1]) * c0 + sigf(gs[0]) * tanh_fast(gs[2]);
            c0 = cn;
            h0_new[(cbase + jl) * BATCH + b] = sigf(gs[3]) * tanh_fast(cn);
        }
        __syncthreads();              // all h0_new stores happen-before tid0's fence
        if (tid == 0) { __threadfence(); atomicAdd(&g_cA, 1u); }

        // ---- layer 1: gates = b1 + W1 @ [h0_new ; h1_old] ----
        // Stage chunk 0's W BEFORE the counter wait (ctr_wait's barp publishes).
#pragma unroll
        for (int i = 0; i < 8; i++) { acc[i][0] = make_float2(0.f, 0.f);
                                      acc[i][1] = make_float2(0.f, 0.f); }

        stage_W(W1, 2 * HIDDEN, s * 256, cbase, Wt, pt);
        const float* hsrc;
        if (s < 4) { ctr_wait(&g_cA, (unsigned)(t + 1) * NCTA, s, pt); hsrc = h0_new; }
        else       { ctr_wait(&g_cB, (unsigned)t * NCTA,       s, pt); hsrc = h1_old; }
        const int kb = (s & 3) * 256;
        gemm128(hsrc + (size_t)kb * 64 + hoff, Wt, rg, acc);
        barp(s);
        stage_W(W1, 2 * HIDDEN, s * 256 + 128, cbase, Wt, pt);
        barp(s);
        gemm128(hsrc + (size_t)(kb + 128) * 64 + hoff, Wt, rg, acc);
        barp(s);
        write_partial(acc, part, rg, bg);
        __syncthreads();
        {
            const float* pb = dsm + (b >> 5) * (32 * PSTR) + (b & 31);
            float gs[4];
#pragma unroll
            for (int q = 0; q < 4; q++) {
                float v = b1r[q];
#pragma unroll
                for (int ss = 0; ss < 8; ss++)
                    v += pb[ss * TILE_F + (q * 8 + jl) * PSTR];
                gs[q] = v;
            }
            float cn = sigf(gs[1]) * c1 + sigf(gs[0]) * tanh_fast(gs[2]);
            c1 = cn;
            h1_new[(cbase + jl) * BATCH + b] = sigf(gs[3]) * tanh_fast(cn);
        }
        __syncthreads();              // all h1_new stores happen-before tid0's fence
        if (tid == 0) { __threadfence(); atomicAdd(&g_cB, 1u); }
    }

    // ---- folded classifier: CTA 0 only, after ALL CTAs' final cB bump ----
    if (blockIdx.x == 0) {
        if (tid == 0) {
            while (*(volatile unsigned*)&g_cB < (unsigned)T_STEPS * NCTA)
                { __nanosleep(64); }
            __threadfence();
        }
        __syncthreads();
        const int sl = tid >> 6;      // j-slice 0..7
        const float* hp = g_h1buf[0] + (size_t)sl * 128 * BATCH + b;
        for (int c = 0; c < NCLS; c++) {
            const float* vr = V + (size_t)c * HIDDEN + sl * 128;
            float a = 0.f;
#pragma unroll 8
            for (int j = 0; j < 128; j++) a += hp[j * BATCH] * vr[j];
            dsm[tid] = a;
            __syncthreads();
            if (tid < 64) {
                float ssum = bV[c];
#pragma unroll
                for (int k2 = 0; k2 < 8; k2++) ssum += dsm[k2 * 64 + tid];
                out[tid * NCLS + c] = ssum;
            }
            __syncthreads();
        }
    }
}

// =====================================================================
extern "C" void kernel_launch(void* const* d_in, const int* in_sizes, int n_in,
                              void* d_out, int out_size)
{
    (void)in_sizes; (void)n_in; (void)out_size;
    const int*   x   = (const int*)d_in[0];
    const float* emb = (const float*)d_in[1];
    const float* W0  = (const float*)d_in[2];
    const float* b0  = (const float*)d_in[3];
    const float* W1  = (const float*)d_in[4];
    const float* b1  = (const float*)d_in[5];
    const float* V   = (const float*)d_in[6];
    const float* bV  = (const float*)d_in[7];
    float* out = (float*)d_out;

    cudaFuncSetAttribute(lstm_persistent,
                         cudaFuncAttributeMaxDynamicSharedMemorySize, SMEM_BYTES);

    precompute_x0<<<dim3(T_STEPS, 64), 128>>>(x, emb, W0, b0);
    lstm_persistent<<<NCTA, 512, SMEM_BYTES>>>(W0, W1, b1, V, bV, out);
}